// round 5
// baseline (speedup 1.0000x reference)
#include <cuda_runtime.h>
#include <cuda_bf16.h>
#include <stdint.h>

#define Gx 106
#define G2x (106 * 106)
#define G3x (106 * 106 * 106)
#define MAXB 2
#define CROP 100
#define CROPV (100 * 100 * 100)
#define MAXPTS (MAXB * 131072)

// Dual-parity scratch, float2 per slot = (grid_sum, acc_sum).
#define SHIFT (MAXB * G3x + 1)
#define NSLOTS (2 * MAXB * G3x + 2)
__device__ float2 g_combo2[NSLOTS];

// Sorting structures
#define SCAN_BLOCKS 73
#define NBINS_PAD (SCAN_BLOCKS * 1024)          // covers (2*G3x)>>5 with slack
__device__ unsigned int g_hist[NBINS_PAD];      // histogram -> exclusive offsets -> cursors
__device__ unsigned int g_blocksum[SCAN_BLOCKS];
__device__ float4 g_staged[MAXPTS];             // (frac0, frac1, frac2, dens)
__device__ int    g_c0sh[MAXPTS];               // c0*2 + parity
__device__ int    g_keys[MAXPTS];
__device__ float4 g_sortedF4[MAXPTS];
__device__ int    g_sortedC0[MAXPTS];

// ---------------------------------------------------------------------------
// K1: zero scratch + histogram (grid-stride, float4/uint4 stores)
// ---------------------------------------------------------------------------
__global__ void __launch_bounds__(256)
splat_zero_kernel(int n4, int h4) {
    int stride = gridDim.x * blockDim.x;
    float4 z = make_float4(0.f, 0.f, 0.f, 0.f);
    for (int i = blockIdx.x * blockDim.x + threadIdx.x; i < n4; i += stride)
        reinterpret_cast<float4*>(g_combo2)[i] = z;
    uint4 uz = make_uint4(0u, 0u, 0u, 0u);
    for (int i = blockIdx.x * blockDim.x + threadIdx.x; i < h4; i += stride)
        reinterpret_cast<uint4*>(g_hist)[i] = uz;
}

// ---------------------------------------------------------------------------
// K2a: per-point prep — fracs, window-start cell c0, parity, sort key, hist
// ---------------------------------------------------------------------------
__global__ void __launch_bounds__(256)
splat_prep_kernel(const float* __restrict__ points,
                  const float* __restrict__ dens,
                  const float* __restrict__ bbox,
                  int total, int Npb) {
    int t = blockIdx.x * blockDim.x + threadIdx.x;
    if (t >= total) return;

    int b = t / Npb;
    float d = __ldg(dens + t);
    float px = __ldg(points + 3 * t + 0);
    float py = __ldg(points + 3 * t + 1);
    float pz = __ldg(points + 3 * t + 2);

    int lo[3];
    float fr[3];
#pragma unroll
    for (int a = 0; a < 3; a++) {
        float c = (a == 0) ? pz : ((a == 1) ? py : px);
        int bd = 2 - a;
        float blo  = __fsub_rn(bbox[bd * 2 + 0], 0.03f);
        float bhi  = __fadd_rn(bbox[bd * 2 + 1], 0.03f);
        float span = __fsub_rn(bhi, blo);
        float tt = __fsub_rn(__fsub_rn(c, blo), 0.005f);
        float pg = __fmul_rn(__fdiv_rn(tt, span), 106.0f);
        float pgr = rintf(pg);           // round-half-even == jnp.round
        int   gi  = (int)pgr;
        float frac = pg - pgr;           // Sterbenz-exact
        fr[a] = frac;
        lo[a] = gi + ((frac < 0.0f) ? -2 : -1);
    }

    int c0 = b * G3x + lo[0] * G2x + lo[1] * Gx + lo[2];
    int sh = lo[2] & 1;
    int key = c0 >> 5;

    g_staged[t] = make_float4(fr[0], fr[1], fr[2], d);
    g_c0sh[t] = c0 * 2 + sh;
    g_keys[t] = key;
    atomicAdd(&g_hist[key], 1u);
}

// ---------------------------------------------------------------------------
// K2b: block-local exclusive scan over histogram (1024/block)
// ---------------------------------------------------------------------------
__global__ void __launch_bounds__(1024)
splat_scan1_kernel() {
    __shared__ unsigned int s[1024];
    int tid = threadIdx.x;
    int idx = blockIdx.x * 1024 + tid;
    unsigned int v = g_hist[idx];
    s[tid] = v;
    __syncthreads();
#pragma unroll
    for (int off = 1; off < 1024; off <<= 1) {
        unsigned int x = (tid >= off) ? s[tid - off] : 0u;
        __syncthreads();
        s[tid] += x;
        __syncthreads();
    }
    g_hist[idx] = s[tid] - v;            // exclusive within block
    if (tid == 1023) g_blocksum[blockIdx.x] = s[1023];
}

// ---------------------------------------------------------------------------
// K2c: add block prefix
// ---------------------------------------------------------------------------
__global__ void __launch_bounds__(1024)
splat_scan2_kernel() {
    __shared__ unsigned int pfx;
    if (threadIdx.x == 0) {
        unsigned int p = 0;
        for (int i = 0; i < (int)blockIdx.x; i++) p += g_blocksum[i];
        pfx = p;
    }
    __syncthreads();
    int idx = blockIdx.x * 1024 + threadIdx.x;
    g_hist[idx] += pfx;
}

// ---------------------------------------------------------------------------
// K3: reorder points into sorted order (destructive cursors in g_hist)
// ---------------------------------------------------------------------------
__global__ void __launch_bounds__(256)
splat_reorder_kernel(int total) {
    int t = blockIdx.x * blockDim.x + threadIdx.x;
    if (t >= total) return;
    int key = g_keys[t];
    unsigned int pos = atomicAdd(&g_hist[key], 1u);
    g_sortedF4[pos] = g_staged[t];
    g_sortedC0[pos] = g_c0sh[t];
}

// ---------------------------------------------------------------------------
// K4: scatter from sorted points. 32 red.v4 per point, coalesced targets.
// ---------------------------------------------------------------------------
__global__ void __launch_bounds__(256)
splat_scatter_kernel(int total) {
    int t = blockIdx.x * blockDim.x + threadIdx.x;
    if (t >= total) return;

    float4 st = g_sortedF4[t];
    int c0sh = g_sortedC0[t];
    int c0 = c0sh >> 1;
    int sh = c0sh & 1;
    float d = st.w;

    float w[3][4];
    float fr[3] = {st.x, st.y, st.z};
#pragma unroll
    for (int a = 0; a < 3; a++) {
        float frac = fr[a];
        int l = (frac < 0.0f) ? -2 : -1;
#pragma unroll
        for (int o = 0; o < 4; o++) {
            float dd = (float)(l + o) - frac;            // exact, matches ref
            w[a][o] = fmaxf(1.0f - fabsf(dd) * 0.5f, 0.0f);
        }
    }
    float w20 = w[2][0], w21 = w[2][1], w22 = w[2][2], w23 = w[2][3];

    float2* base = g_combo2 + ((size_t)c0 + (sh ? (size_t)SHIFT : (size_t)0));

#pragma unroll
    for (int i = 0; i < 4; i++) {
        float w0 = w[0][i];
#pragma unroll
        for (int j = 0; j < 4; j++) {
            float wij  = w0 * w[1][j];
            float wijd = wij * d;
            float2* p = base + i * G2x + j * Gx;

            asm volatile("red.global.add.v4.f32 [%0], {%1, %2, %3, %4};"
                         :: "l"(p),
                            "f"(wijd * w20), "f"(wij * w20),
                            "f"(wijd * w21), "f"(wij * w21)
                         : "memory");
            asm volatile("red.global.add.v4.f32 [%0], {%1, %2, %3, %4};"
                         :: "l"(p + 2),
                            "f"(wijd * w22), "f"(wij * w22),
                            "f"(wijd * w23), "f"(wij * w23)
                         : "memory");
        }
    }
}

// ---------------------------------------------------------------------------
// K5: finalize — read-only crop, fast divide, coalesced float4 stores
// ---------------------------------------------------------------------------
__global__ void __launch_bounds__(256)
splat_finalize_kernel(float* __restrict__ out, int B, int writeAcc) {
    int q = blockIdx.x * blockDim.x + threadIdx.x;
    int tot = B * CROPV;
    int tot4 = tot >> 2;
    if (q >= tot4) return;
    int o = q << 2;

    int b = o / CROPV;
    int r = o - b * CROPV;
    int i = r / (CROP * CROP);
    int rem = r - i * (CROP * CROP);
    int j = rem / CROP;
    int k = rem - j * CROP;

    int src = b * G3x + (i + 3) * G2x + (j + 3) * Gx + (k + 3);
    const float2* __restrict__ p0 = g_combo2 + src;
    const float2* __restrict__ p1 = g_combo2 + SHIFT + src;

    float4 go, ao;
#pragma unroll
    for (int u = 0; u < 4; u++) {
        float2 c0 = __ldg(p0 + u);
        float2 c1 = __ldg(p1 + u);
        float g = c0.x + c1.x;
        float a = c0.y + c1.y;
        float v = (a > 0.0f) ? __fdividef(g, a + 1e-9f) : g;
        if (u == 0) { go.x = v; ao.x = a; }
        if (u == 1) { go.y = v; ao.y = a; }
        if (u == 2) { go.z = v; ao.z = a; }
        if (u == 3) { go.w = v; ao.w = a; }
    }
    *reinterpret_cast<float4*>(out + o) = go;
    if (writeAcc) *reinterpret_cast<float4*>(out + tot + o) = ao;
}

// ---------------------------------------------------------------------------
extern "C" void kernel_launch(void* const* d_in, const int* in_sizes, int n_in,
                              void* d_out, int out_size) {
    const float* points = (const float*)d_in[0];
    const float* dens   = (const float*)d_in[1];
    const float* bbox   = (const float*)d_in[2];
    float* out = (float*)d_out;

    int total = in_sizes[1];              // B * N
    int B = total / 131072;
    if (B < 1) B = 1;
    if (B > MAXB) B = MAXB;
    int Npb = total / B;

    int writeAcc = (out_size >= 2 * B * CROPV) ? 1 : 0;
    int tpb = 256;

    // K1: zero scratch + histogram
    {
        int n4 = NSLOTS / 2;
        int h4 = NBINS_PAD / 4;
        splat_zero_kernel<<<1184, tpb>>>(n4, h4);
    }
    // K2a: prep + histogram
    splat_prep_kernel<<<(total + tpb - 1) / tpb, tpb>>>(points, dens, bbox,
                                                        total, Npb);
    // K2b/K2c: scan
    splat_scan1_kernel<<<SCAN_BLOCKS, 1024>>>();
    splat_scan2_kernel<<<SCAN_BLOCKS, 1024>>>();
    // K3: reorder
    splat_reorder_kernel<<<(total + tpb - 1) / tpb, tpb>>>(total);
    // K4: scatter
    splat_scatter_kernel<<<(total + tpb - 1) / tpb, tpb>>>(total);
    // K5: finalize
    {
        int tot4 = (B * CROPV) >> 2;
        splat_finalize_kernel<<<(tot4 + tpb - 1) / tpb, tpb>>>(out, B, writeAcc);
    }
}

// round 7
// speedup vs baseline: 1.2263x; 1.2263x over previous
#include <cuda_runtime.h>
#include <cuda_bf16.h>
#include <stdint.h>

#define Gx 106
#define G2x (106 * 106)
#define G3x (106 * 106 * 106)
#define MAXB 2
#define CROP 100
#define CROPV (100 * 100 * 100)

// Dual-parity scratch, float2 per slot = (grid_sum, acc_sum).
//   P0: cell c -> slot c            (even c 16B-aligned)
//   P1: cell c -> slot SHIFT + c    (odd  c 16B-aligned; SHIFT is odd)
#define SHIFT (MAXB * G3x + 1)
#define NSLOTS (2 * MAXB * G3x + 2)
__device__ float2 g_combo2[NSLOTS];   // zero at module load; re-zeroed per replay

// ---------------------------------------------------------------------------
// Zero the scratch. 512 tpb, one float4 per thread, exact fit.
// ---------------------------------------------------------------------------
__global__ void __launch_bounds__(512)
splat_zero_kernel(int n4) {
    int i = blockIdx.x * blockDim.x + threadIdx.x;
    if (i < n4) {
        float4* p = reinterpret_cast<float4*>(g_combo2) + i;
        asm volatile("st.global.cs.v4.f32 [%0], {%1, %1, %1, %1};"
                     :: "l"(p), "f"(0.0f) : "memory");
    }
}

// ---------------------------------------------------------------------------
// Scatter: one thread per point. 4x4x4 window, exactly 32 red.v4 per point.
// Parity of the k window start selects the scratch copy -> always 16B aligned.
// At the REDG issue floor (~1.29 cyc/lane/SM); do not touch.
// ---------------------------------------------------------------------------
__global__ void __launch_bounds__(256)
splat_scatter_kernel(const float* __restrict__ points,
                     const float* __restrict__ dens,
                     const float* __restrict__ bbox,
                     int total, int Npb) {
    int t = blockIdx.x * blockDim.x + threadIdx.x;
    if (t >= total) return;

    int b = t / Npb;
    float d = __ldg(dens + t);

    float px = __ldg(points + 3 * t + 0);
    float py = __ldg(points + 3 * t + 1);
    float pz = __ldg(points + 3 * t + 2);

    int lo[3];
    float w[3][4];

    // Grid axis a uses point coordinate (2 - a) and bbox row (2 - a)
    // (the reference reverses the last dim of both points and bbox).
#pragma unroll
    for (int a = 0; a < 3; a++) {
        float c = (a == 0) ? pz : ((a == 1) ? py : px);
        int bd = 2 - a;
        float blo  = __fsub_rn(bbox[bd * 2 + 0], 0.03f);   // pad = (KR+1)*CELL
        float bhi  = __fadd_rn(bbox[bd * 2 + 1], 0.03f);
        float span = __fsub_rn(bhi, blo);
        // pg = ((c - blo) - CELL/2) / span * G   (op-for-op, IEEE rn)
        float tt = __fsub_rn(__fsub_rn(c, blo), 0.005f);
        float pg = __fmul_rn(__fdiv_rn(tt, span), 106.0f);
        float pgr = rintf(pg);           // round-half-even == jnp.round
        int   gi  = (int)pgr;
        float frac = pg - pgr;           // Sterbenz-exact

        // Only one of offsets -2/+2 is nonzero -> 4-wide window.
        int l = (frac < 0.0f) ? -2 : -1;
        lo[a] = gi + l;
#pragma unroll
        for (int o = 0; o < 4; o++) {
            float dd = (float)(l + o) - frac;            // exact
            w[a][o] = fmaxf(1.0f - fabsf(dd) * 0.5f, 0.0f);
        }
    }

    float w20 = w[2][0], w21 = w[2][1], w22 = w[2][2], w23 = w[2][3];

    int c0 = b * G3x + lo[0] * G2x + lo[1] * Gx + lo[2];  // window-start cell
    int sh = lo[2] & 1;                                    // parity -> copy select
    float2* base = g_combo2 + ((size_t)c0 + (sh ? (size_t)SHIFT : (size_t)0));

#pragma unroll
    for (int i = 0; i < 4; i++) {
        float w0 = w[0][i];
#pragma unroll
        for (int j = 0; j < 4; j++) {
            float wij  = w0 * w[1][j];
            float wijd = wij * d;
            float2* p = base + i * G2x + j * Gx;

            asm volatile("red.global.add.v4.f32 [%0], {%1, %2, %3, %4};"
                         :: "l"(p),
                            "f"(wijd * w20), "f"(wij * w20),
                            "f"(wijd * w21), "f"(wij * w21)
                         : "memory");
            asm volatile("red.global.add.v4.f32 [%0], {%1, %2, %3, %4};"
                         :: "l"(p + 2),
                            "f"(wijd * w22), "f"(wij * w22),
                            "f"(wijd * w23), "f"(wij * w23)
                         : "memory");
        }
    }
}

// ---------------------------------------------------------------------------
// Finalize: read-only over the CROP region. 8 k-cells per thread;
// each 4-cell quad re-derives (j,k) with at most one row carry.
// ---------------------------------------------------------------------------
__global__ void __launch_bounds__(256)
splat_finalize_kernel(float* __restrict__ out, int B, int writeAcc) {
    int q = blockIdx.x * blockDim.x + threadIdx.x;
    int tot = B * CROPV;
    int tot8 = tot >> 3;                 // CROPV % 8 == 0
    if (q >= tot8) return;
    int o = q << 3;

    int b = o / CROPV;
    int r = o - b * CROPV;
    int i = r / (CROP * CROP);
    int rem = r - i * (CROP * CROP);
    int j = rem / CROP;
    int k = rem - j * CROP;

#pragma unroll
    for (int h = 0; h < 2; h++) {
        int oo = o + 4 * h;
        int kk = k + 4 * h;
        int jj = j, ii = i, bb = b;
        if (kk >= CROP) {                // row carry (at most one)
            kk -= CROP; jj += 1;
            if (jj >= CROP) { jj = 0; ii += 1; }
            if (ii >= CROP) { ii = 0; bb += 1; }
        }
        int src = bb * G3x + (ii + 3) * G2x + (jj + 3) * Gx + (kk + 3);
        const float2* __restrict__ p0 = g_combo2 + src;
        const float2* __restrict__ p1 = g_combo2 + SHIFT + src;

        float4 go, ao;
#pragma unroll
        for (int u = 0; u < 4; u++) {
            float2 c0 = __ldg(p0 + u);
            float2 c1 = __ldg(p1 + u);
            float g = c0.x + c1.x;
            float a = c0.y + c1.y;
            float v = (a > 0.0f) ? __fdividef(g, a + 1e-9f) : g;
            if (u == 0) { go.x = v; ao.x = a; }
            if (u == 1) { go.y = v; ao.y = a; }
            if (u == 2) { go.z = v; ao.z = a; }
            if (u == 3) { go.w = v; ao.w = a; }
        }
        *reinterpret_cast<float4*>(out + oo) = go;
        if (writeAcc) *reinterpret_cast<float4*>(out + tot + oo) = ao;
    }
}

// ---------------------------------------------------------------------------
extern "C" void kernel_launch(void* const* d_in, const int* in_sizes, int n_in,
                              void* d_out, int out_size) {
    const float* points = (const float*)d_in[0];
    const float* dens   = (const float*)d_in[1];
    const float* bbox   = (const float*)d_in[2];
    float* out = (float*)d_out;

    int total = in_sizes[1];              // B * N
    int B = total / 131072;
    if (B < 1) B = 1;
    if (B > MAXB) B = MAXB;
    int Npb = total / B;

    int writeAcc = (out_size >= 2 * B * CROPV) ? 1 : 0;

    // 1) zero scratch
    {
        int n4 = NSLOTS / 2;              // float4 count (NSLOTS even)
        int tpb = 512;
        splat_zero_kernel<<<(n4 + tpb - 1) / tpb, tpb>>>(n4);
    }
    // 2) scatter
    {
        int tpb = 256;
        splat_scatter_kernel<<<(total + tpb - 1) / tpb, tpb>>>(points, dens, bbox,
                                                               total, Npb);
    }
    // 3) normalize + crop + write
    {
        int tot8 = (B * CROPV) >> 3;
        int tpb = 256;
        splat_finalize_kernel<<<(tot8 + tpb - 1) / tpb, tpb>>>(out, B, writeAcc);
    }
}

// round 8
// speedup vs baseline: 1.2759x; 1.0404x over previous
#include <cuda_runtime.h>
#include <cuda_bf16.h>
#include <stdint.h>

#define Gx 106
#define G2x (106 * 106)
#define G3x (106 * 106 * 106)
#define MAXB 2
#define CROP 100
#define CROPV (100 * 100 * 100)

// Dual-parity scratch, float2 per slot = (grid_sum, acc_sum).
//   P0: cell c -> slot c            (even c 16B-aligned)
//   P1: cell c -> slot SHIFT + c    (odd  c 16B-aligned; SHIFT is odd)
#define SHIFT (MAXB * G3x + 1)
#define NSLOTS (2 * MAXB * G3x + 2)
__device__ float2 g_combo2[NSLOTS];   // zeroed by memset node every replay

// ---------------------------------------------------------------------------
// Scatter: one thread per point. 4x4x4 window, exactly 32 red.v4 per point.
// Parity of the k window start selects the scratch copy -> always 16B aligned.
// At the red issue floor (~1.27 cyc per 16B red per SM); do not touch.
// ---------------------------------------------------------------------------
__global__ void __launch_bounds__(256)
splat_scatter_kernel(const float* __restrict__ points,
                     const float* __restrict__ dens,
                     const float* __restrict__ bbox,
                     int total, int Npb) {
    int t = blockIdx.x * blockDim.x + threadIdx.x;
    if (t >= total) return;

    int b = t / Npb;
    float d = __ldg(dens + t);

    float px = __ldg(points + 3 * t + 0);
    float py = __ldg(points + 3 * t + 1);
    float pz = __ldg(points + 3 * t + 2);

    int lo[3];
    float w[3][4];

    // Grid axis a uses point coordinate (2 - a) and bbox row (2 - a)
    // (the reference reverses the last dim of both points and bbox).
#pragma unroll
    for (int a = 0; a < 3; a++) {
        float c = (a == 0) ? pz : ((a == 1) ? py : px);
        int bd = 2 - a;
        float blo  = __fsub_rn(bbox[bd * 2 + 0], 0.03f);   // pad = (KR+1)*CELL
        float bhi  = __fadd_rn(bbox[bd * 2 + 1], 0.03f);
        float span = __fsub_rn(bhi, blo);
        // pg = ((c - blo) - CELL/2) / span * G   (op-for-op, IEEE rn)
        float tt = __fsub_rn(__fsub_rn(c, blo), 0.005f);
        float pg = __fmul_rn(__fdiv_rn(tt, span), 106.0f);
        float pgr = rintf(pg);           // round-half-even == jnp.round
        int   gi  = (int)pgr;
        float frac = pg - pgr;           // Sterbenz-exact

        // Only one of offsets -2/+2 is nonzero -> 4-wide window.
        int l = (frac < 0.0f) ? -2 : -1;
        lo[a] = gi + l;
#pragma unroll
        for (int o = 0; o < 4; o++) {
            float dd = (float)(l + o) - frac;            // exact
            w[a][o] = fmaxf(1.0f - fabsf(dd) * 0.5f, 0.0f);
        }
    }

    float w20 = w[2][0], w21 = w[2][1], w22 = w[2][2], w23 = w[2][3];

    int c0 = b * G3x + lo[0] * G2x + lo[1] * Gx + lo[2];  // window-start cell
    int sh = lo[2] & 1;                                    // parity -> copy select
    float2* base = g_combo2 + ((size_t)c0 + (sh ? (size_t)SHIFT : (size_t)0));

#pragma unroll
    for (int i = 0; i < 4; i++) {
        float w0 = w[0][i];
#pragma unroll
        for (int j = 0; j < 4; j++) {
            float wij  = w0 * w[1][j];
            float wijd = wij * d;
            float2* p = base + i * G2x + j * Gx;

            asm volatile("red.global.add.v4.f32 [%0], {%1, %2, %3, %4};"
                         :: "l"(p),
                            "f"(wijd * w20), "f"(wij * w20),
                            "f"(wijd * w21), "f"(wij * w21)
                         : "memory");
            asm volatile("red.global.add.v4.f32 [%0], {%1, %2, %3, %4};"
                         :: "l"(p + 2),
                            "f"(wijd * w22), "f"(wij * w22),
                            "f"(wijd * w23), "f"(wij * w23)
                         : "memory");
        }
    }
}

// ---------------------------------------------------------------------------
// Finalize: read-only over the CROP region. 4 k-cells per thread (R4 form).
// P0+P1 sum, fast-divide normalize, coalesced float4 output stores.
// ---------------------------------------------------------------------------
__global__ void __launch_bounds__(256)
splat_finalize_kernel(float* __restrict__ out, int B, int writeAcc) {
    int q = blockIdx.x * blockDim.x + threadIdx.x;
    int tot = B * CROPV;
    int tot4 = tot >> 2;
    if (q >= tot4) return;
    int o = q << 2;

    int b = o / CROPV;
    int r = o - b * CROPV;
    int i = r / (CROP * CROP);
    int rem = r - i * (CROP * CROP);
    int j = rem / CROP;
    int k = rem - j * CROP;            // multiple of 4

    int src = b * G3x + (i + 3) * G2x + (j + 3) * Gx + (k + 3);
    const float2* __restrict__ p0 = g_combo2 + src;
    const float2* __restrict__ p1 = g_combo2 + SHIFT + src;

    float4 go, ao;
#pragma unroll
    for (int u = 0; u < 4; u++) {
        float2 c0 = __ldg(p0 + u);
        float2 c1 = __ldg(p1 + u);
        float g = c0.x + c1.x;
        float a = c0.y + c1.y;
        float v = (a > 0.0f) ? __fdividef(g, a + 1e-9f) : g;
        if (u == 0) { go.x = v; ao.x = a; }
        if (u == 1) { go.y = v; ao.y = a; }
        if (u == 2) { go.z = v; ao.z = a; }
        if (u == 3) { go.w = v; ao.w = a; }
    }
    *reinterpret_cast<float4*>(out + o) = go;
    if (writeAcc) *reinterpret_cast<float4*>(out + tot + o) = ao;
}

// ---------------------------------------------------------------------------
extern "C" void kernel_launch(void* const* d_in, const int* in_sizes, int n_in,
                              void* d_out, int out_size) {
    const float* points = (const float*)d_in[0];
    const float* dens   = (const float*)d_in[1];
    const float* bbox   = (const float*)d_in[2];
    float* out = (float*)d_out;

    int total = in_sizes[1];              // B * N
    int B = total / 131072;
    if (B < 1) B = 1;
    if (B > MAXB) B = MAXB;
    int Npb = total / B;

    int writeAcc = (out_size >= 2 * B * CROPV) ? 1 : 0;

    // 1) zero scratch via driver memset (memset node under graph capture;
    //    no allocation, no sync). Symbol lookup is a no-enqueue API.
    {
        void* scratch = nullptr;
        cudaGetSymbolAddress(&scratch, g_combo2);
        cudaMemsetAsync(scratch, 0, (size_t)NSLOTS * sizeof(float2), 0);
    }
    // 2) scatter
    {
        int tpb = 256;
        splat_scatter_kernel<<<(total + tpb - 1) / tpb, tpb>>>(points, dens, bbox,
                                                               total, Npb);
    }
    // 3) normalize + crop + write
    {
        int tot4 = (B * CROPV) >> 2;
        int tpb = 256;
        splat_finalize_kernel<<<(tot4 + tpb - 1) / tpb, tpb>>>(out, B, writeAcc);
    }
}

// round 9
// speedup vs baseline: 1.3214x; 1.0357x over previous
#include <cuda_runtime.h>
#include <cuda_bf16.h>
#include <stdint.h>

#define Gx 106
#define G2x (106 * 106)
#define G3x (106 * 106 * 106)
#define MAXB 2
#define CROP 100
#define CROPV (100 * 100 * 100)

// Dual-parity scratch, float2 per slot = (grid_sum, acc_sum).
//   P0: cell c -> slot c            (even c 16B-aligned)
//   P1: cell c -> slot SHIFT + c    (odd  c 16B-aligned; SHIFT is odd)
#define SHIFT (MAXB * G3x + 1)
#define NSLOTS (2 * MAXB * G3x + 2)
__device__ float2 g_combo2[NSLOTS];   // re-zeroed every replay (plain stores
                                      // -> lines stay L2-dirty for the reds)

// ---------------------------------------------------------------------------
// Zero the scratch. 4 independent st.v4 per thread (ILP), default .wb caching
// so zeros are L2-resident when the scatter's atomics arrive.
// ---------------------------------------------------------------------------
__global__ void __launch_bounds__(256)
splat_zero_kernel(int n4) {
    int i0 = (blockIdx.x * 256) * 4 + threadIdx.x;
    float4* p = reinterpret_cast<float4*>(g_combo2);
    float4 z = make_float4(0.f, 0.f, 0.f, 0.f);
#pragma unroll
    for (int u = 0; u < 4; u++) {
        int i = i0 + u * 256;
        if (i < n4) p[i] = z;
    }
}

// ---------------------------------------------------------------------------
// Scatter: one thread per point. 4x4x4 window, exactly 32 red.v4 per point.
// Parity of the k window start selects the scratch copy -> always 16B aligned.
// Measured AT the per-SM REDG spread-issue floor (1.29 cyc/lane); closed.
// ---------------------------------------------------------------------------
__global__ void __launch_bounds__(256)
splat_scatter_kernel(const float* __restrict__ points,
                     const float* __restrict__ dens,
                     const float* __restrict__ bbox,
                     int total, int Npb) {
    int t = blockIdx.x * blockDim.x + threadIdx.x;
    if (t >= total) return;

    int b = t / Npb;
    float d = __ldg(dens + t);

    float px = __ldg(points + 3 * t + 0);
    float py = __ldg(points + 3 * t + 1);
    float pz = __ldg(points + 3 * t + 2);

    int lo[3];
    float w[3][4];

    // Grid axis a uses point coordinate (2 - a) and bbox row (2 - a)
    // (the reference reverses the last dim of both points and bbox).
#pragma unroll
    for (int a = 0; a < 3; a++) {
        float c = (a == 0) ? pz : ((a == 1) ? py : px);
        int bd = 2 - a;
        float blo  = __fsub_rn(bbox[bd * 2 + 0], 0.03f);   // pad = (KR+1)*CELL
        float bhi  = __fadd_rn(bbox[bd * 2 + 1], 0.03f);
        float span = __fsub_rn(bhi, blo);
        // pg = ((c - blo) - CELL/2) / span * G   (op-for-op, IEEE rn)
        float tt = __fsub_rn(__fsub_rn(c, blo), 0.005f);
        float pg = __fmul_rn(__fdiv_rn(tt, span), 106.0f);
        float pgr = rintf(pg);           // round-half-even == jnp.round
        int   gi  = (int)pgr;
        float frac = pg - pgr;           // Sterbenz-exact

        // Only one of offsets -2/+2 is nonzero -> 4-wide window.
        int l = (frac < 0.0f) ? -2 : -1;
        lo[a] = gi + l;
#pragma unroll
        for (int o = 0; o < 4; o++) {
            float dd = (float)(l + o) - frac;            // exact
            w[a][o] = fmaxf(1.0f - fabsf(dd) * 0.5f, 0.0f);
        }
    }

    float w20 = w[2][0], w21 = w[2][1], w22 = w[2][2], w23 = w[2][3];

    int c0 = b * G3x + lo[0] * G2x + lo[1] * Gx + lo[2];  // window-start cell
    int sh = lo[2] & 1;                                    // parity -> copy select
    float2* base = g_combo2 + ((size_t)c0 + (sh ? (size_t)SHIFT : (size_t)0));

#pragma unroll
    for (int i = 0; i < 4; i++) {
        float w0 = w[0][i];
#pragma unroll
        for (int j = 0; j < 4; j++) {
            float wij  = w0 * w[1][j];
            float wijd = wij * d;
            float2* p = base + i * G2x + j * Gx;

            asm volatile("red.global.add.v4.f32 [%0], {%1, %2, %3, %4};"
                         :: "l"(p),
                            "f"(wijd * w20), "f"(wij * w20),
                            "f"(wijd * w21), "f"(wij * w21)
                         : "memory");
            asm volatile("red.global.add.v4.f32 [%0], {%1, %2, %3, %4};"
                         :: "l"(p + 2),
                            "f"(wijd * w22), "f"(wij * w22),
                            "f"(wijd * w23), "f"(wij * w23)
                         : "memory");
        }
    }
}

// ---------------------------------------------------------------------------
// Finalize: read-only over the CROP region. 4 k-cells per thread (R4 form —
// measured best). P0+P1 sum, fast-divide normalize, float4 output stores.
// ---------------------------------------------------------------------------
__global__ void __launch_bounds__(256)
splat_finalize_kernel(float* __restrict__ out, int B, int writeAcc) {
    int q = blockIdx.x * blockDim.x + threadIdx.x;
    int tot = B * CROPV;
    int tot4 = tot >> 2;
    if (q >= tot4) return;
    int o = q << 2;

    int b = o / CROPV;
    int r = o - b * CROPV;
    int i = r / (CROP * CROP);
    int rem = r - i * (CROP * CROP);
    int j = rem / CROP;
    int k = rem - j * CROP;            // multiple of 4

    int src = b * G3x + (i + 3) * G2x + (j + 3) * Gx + (k + 3);
    const float2* __restrict__ p0 = g_combo2 + src;
    const float2* __restrict__ p1 = g_combo2 + SHIFT + src;

    float4 go, ao;
#pragma unroll
    for (int u = 0; u < 4; u++) {
        float2 c0 = __ldg(p0 + u);
        float2 c1 = __ldg(p1 + u);
        float g = c0.x + c1.x;
        float a = c0.y + c1.y;
        float v = (a > 0.0f) ? __fdividef(g, a + 1e-9f) : g;
        if (u == 0) { go.x = v; ao.x = a; }
        if (u == 1) { go.y = v; ao.y = a; }
        if (u == 2) { go.z = v; ao.z = a; }
        if (u == 3) { go.w = v; ao.w = a; }
    }
    *reinterpret_cast<float4*>(out + o) = go;
    if (writeAcc) *reinterpret_cast<float4*>(out + tot + o) = ao;
}

// ---------------------------------------------------------------------------
extern "C" void kernel_launch(void* const* d_in, const int* in_sizes, int n_in,
                              void* d_out, int out_size) {
    const float* points = (const float*)d_in[0];
    const float* dens   = (const float*)d_in[1];
    const float* bbox   = (const float*)d_in[2];
    float* out = (float*)d_out;

    int total = in_sizes[1];              // B * N
    int B = total / 131072;
    if (B < 1) B = 1;
    if (B > MAXB) B = MAXB;
    int Npb = total / B;

    int writeAcc = (out_size >= 2 * B * CROPV) ? 1 : 0;

    // 1) zero scratch (plain stores -> L2-resident zeros for the scatter)
    {
        int n4 = NSLOTS / 2;              // float4 count (NSLOTS even)
        int per_blk = 256 * 4;
        splat_zero_kernel<<<(n4 + per_blk - 1) / per_blk, 256>>>(n4);
    }
    // 2) scatter
    {
        int tpb = 256;
        splat_scatter_kernel<<<(total + tpb - 1) / tpb, tpb>>>(points, dens, bbox,
                                                               total, Npb);
    }
    // 3) normalize + crop + write
    {
        int tot4 = (B * CROPV) >> 2;
        int tpb = 256;
        splat_finalize_kernel<<<(tot4 + tpb - 1) / tpb, tpb>>>(out, B, writeAcc);
    }
}